// round 3
// baseline (speedup 1.0000x reference)
#include <cuda_runtime.h>

#define B_   4
#define N_   4096
#define DIN_ 128
#define H_   64
#define DO_  128
#define BM   64
#define BN   64
#define QS   68   // padded smem row stride (floats), multiple of 4 for float4

// Scratch for projected Q, K, V (device globals: no allocation allowed)
__device__ float g_Q[B_ * N_ * H_];
__device__ float g_K[B_ * N_ * H_];
__device__ float g_V[B_ * N_ * DO_];

// ---------------------------------------------------------------------------
// Stage 1: Q = h@Ws, K = h@Wt, V = h@Wc   (fused; 4 rows per CTA)
// threads 0..63 -> Q cols, 64..127 -> K cols, 128..255 -> V cols (warp-uniform)
// ---------------------------------------------------------------------------
__global__ __launch_bounds__(256) void proj_kernel(
    const float* __restrict__ h, const float* __restrict__ Ws,
    const float* __restrict__ Wt, const float* __restrict__ Wc) {
    __shared__ float sh[4][DIN_];
    const int row0 = blockIdx.x * 4;
    const int tid = threadIdx.x;

    #pragma unroll
    for (int i = tid; i < 4 * DIN_; i += 256)
        sh[i >> 7][i & 127] = h[(size_t)row0 * DIN_ + i];
    __syncthreads();

    const int c = tid;
    const float* W; float* dst; int col, stride;
    if (c < 64)       { W = Ws; dst = g_Q; col = c;       stride = H_;  }
    else if (c < 128) { W = Wt; dst = g_K; col = c - 64;  stride = H_;  }
    else              { W = Wc; dst = g_V; col = c - 128; stride = DO_; }

    float a0 = 0.f, a1 = 0.f, a2 = 0.f, a3 = 0.f;
    const float* wp = W + col;
    #pragma unroll 16
    for (int k = 0; k < DIN_; ++k) {
        float w = wp[k * stride];
        a0 = fmaf(sh[0][k], w, a0);
        a1 = fmaf(sh[1][k], w, a1);
        a2 = fmaf(sh[2][k], w, a2);
        a3 = fmaf(sh[3][k], w, a3);
    }
    dst[(size_t)(row0 + 0) * stride + col] = a0;
    dst[(size_t)(row0 + 1) * stride + col] = a1;
    dst[(size_t)(row0 + 2) * stride + col] = a2;
    dst[(size_t)(row0 + 3) * stride + col] = a3;
}

// ---------------------------------------------------------------------------
// Stage 2: flash attention with adjacency mask.
// Grid (N/BM, B), 256 threads. ty=tid/16 (4 rows each), tx=tid%16.
// S-phase: 4x4 micro-tile of S[64x64]; PV-phase: 4 rows x 8 dims of acc[64x128].
// ---------------------------------------------------------------------------
extern __shared__ float smem[];

__global__ __launch_bounds__(256, 2) void attn_kernel(
    const int* __restrict__ adj, float* __restrict__ out) {
    float* sQ = smem;                 // [64][QS] k-major: sQ[k*QS + r]
    float* sK = sQ + 64 * QS;         // [64][QS] k-major: sK[k*QS + c]
    float* sP = sK + 64 * QS;         // [64][QS] row-major: sP[r*QS + j]
    float* sV = sP + 64 * QS;         // [64][128]

    const int b    = blockIdx.y;
    const int row0 = blockIdx.x * BM;
    const int tid  = threadIdx.x;
    const int ty   = tid >> 4;
    const int tx   = tid & 15;

    const float* Qg = g_Q + (size_t)b * N_ * H_;
    const float* Kg = g_K + (size_t)b * N_ * H_;
    const float* Vg = g_V + (size_t)b * N_ * DO_;

    // Load Q tile transposed into smem (k-major)
    #pragma unroll
    for (int i = tid; i < 64 * 16; i += 256) {
        int r = i >> 4, k4 = (i & 15) << 2;
        float4 q = *reinterpret_cast<const float4*>(Qg + (size_t)(row0 + r) * H_ + k4);
        sQ[(k4 + 0) * QS + r] = q.x;
        sQ[(k4 + 1) * QS + r] = q.y;
        sQ[(k4 + 2) * QS + r] = q.z;
        sQ[(k4 + 3) * QS + r] = q.w;
    }

    float m[4], l[4], acc[4][8];
    #pragma unroll
    for (int i = 0; i < 4; ++i) {
        m[i] = -1e30f; l[i] = 0.f;
        #pragma unroll
        for (int d = 0; d < 8; ++d) acc[i][d] = 0.f;
    }

    for (int jb = 0; jb < N_ / BN; ++jb) {
        const int c0 = jb * BN;
        __syncthreads();   // prior PV done (and Q load on first iter)

        // Load K tile transposed (k-major) + V tile (row-major)
        #pragma unroll
        for (int i = tid; i < 64 * 16; i += 256) {
            int r = i >> 4, k4 = (i & 15) << 2;
            float4 kk = *reinterpret_cast<const float4*>(Kg + (size_t)(c0 + r) * H_ + k4);
            sK[(k4 + 0) * QS + r] = kk.x;
            sK[(k4 + 1) * QS + r] = kk.y;
            sK[(k4 + 2) * QS + r] = kk.z;
            sK[(k4 + 3) * QS + r] = kk.w;
        }
        #pragma unroll
        for (int i = tid; i < 64 * 32; i += 256) {
            int r = i >> 5, d4 = (i & 31) << 2;
            *reinterpret_cast<float4*>(sV + r * DO_ + d4) =
                *reinterpret_cast<const float4*>(Vg + (size_t)(c0 + r) * DO_ + d4);
        }
        __syncthreads();

        // ---- S = Q @ K^T (4x4 per thread) ----
        float s[4][4];
        #pragma unroll
        for (int i = 0; i < 4; ++i)
            #pragma unroll
            for (int j = 0; j < 4; ++j) s[i][j] = 0.f;

        const float* qb = sQ + 4 * ty;
        const float* kb = sK + 4 * tx;
        #pragma unroll 16
        for (int k = 0; k < 64; ++k) {
            float4 a  = *reinterpret_cast<const float4*>(qb + k * QS);
            float4 bv = *reinterpret_cast<const float4*>(kb + k * QS);
            float av[4] = {a.x, a.y, a.z, a.w};
            float bw[4] = {bv.x, bv.y, bv.z, bv.w};
            #pragma unroll
            for (int i = 0; i < 4; ++i)
                #pragma unroll
                for (int j = 0; j < 4; ++j)
                    s[i][j] = fmaf(av[i], bw[j], s[i][j]);
        }

        // ---- mask + online softmax ----
        #pragma unroll
        for (int i = 0; i < 4; ++i) {
            int4 ab = *reinterpret_cast<const int4*>(
                adj + (size_t)(row0 + 4 * ty + i) * N_ + c0 + 4 * tx);
            float t0 = (ab.x > 0) ? s[i][0] : -1e30f;
            float t1 = (ab.y > 0) ? s[i][1] : -1e30f;
            float t2 = (ab.z > 0) ? s[i][2] : -1e30f;
            float t3 = (ab.w > 0) ? s[i][3] : -1e30f;
            float rm = fmaxf(fmaxf(t0, t1), fmaxf(t2, t3));
            #pragma unroll
            for (int off = 8; off > 0; off >>= 1)
                rm = fmaxf(rm, __shfl_xor_sync(0xffffffffu, rm, off));

            float mn = fmaxf(m[i], rm);
            float sc = __expf(m[i] - mn);

            float p0 = (ab.x > 0) ? __expf(s[i][0] - mn) : 0.f;
            float p1 = (ab.y > 0) ? __expf(s[i][1] - mn) : 0.f;
            float p2 = (ab.z > 0) ? __expf(s[i][2] - mn) : 0.f;
            float p3 = (ab.w > 0) ? __expf(s[i][3] - mn) : 0.f;
            *reinterpret_cast<float4*>(sP + (4 * ty + i) * QS + 4 * tx) =
                make_float4(p0, p1, p2, p3);

            float rsum = (p0 + p1) + (p2 + p3);
            #pragma unroll
            for (int off = 8; off > 0; off >>= 1)
                rsum += __shfl_xor_sync(0xffffffffu, rsum, off);

            l[i] = l[i] * sc + rsum;
            m[i] = mn;
            #pragma unroll
            for (int d = 0; d < 8; ++d) acc[i][d] *= sc;
        }
        __syncthreads();

        // ---- PV: acc[4 rows][8 dims] += P @ V ----
        const float* pBase = sP + 4 * ty * QS;
        const float* vBase = sV + 8 * tx;
        #pragma unroll 8
        for (int j = 0; j < 64; ++j) {
            float p0 = pBase[0 * QS + j];
            float p1 = pBase[1 * QS + j];
            float p2 = pBase[2 * QS + j];
            float p3 = pBase[3 * QS + j];
            float4 v0 = *reinterpret_cast<const float4*>(vBase + j * DO_);
            float4 v1 = *reinterpret_cast<const float4*>(vBase + j * DO_ + 4);
            float vv[8] = {v0.x, v0.y, v0.z, v0.w, v1.x, v1.y, v1.z, v1.w};
            float pp[4] = {p0, p1, p2, p3};
            #pragma unroll
            for (int i = 0; i < 4; ++i)
                #pragma unroll
                for (int d = 0; d < 8; ++d)
                    acc[i][d] = fmaf(pp[i], vv[d], acc[i][d]);
        }
    }

    // ---- epilogue: out = acc / l ----
    #pragma unroll
    for (int i = 0; i < 4; ++i) {
        float inv = 1.0f / l[i];
        float* op = out + ((size_t)b * N_ + row0 + 4 * ty + i) * DO_ + 8 * tx;
        float4 o0 = make_float4(acc[i][0] * inv, acc[i][1] * inv,
                                acc[i][2] * inv, acc[i][3] * inv);
        float4 o1 = make_float4(acc[i][4] * inv, acc[i][5] * inv,
                                acc[i][6] * inv, acc[i][7] * inv);
        *reinterpret_cast<float4*>(op)     = o0;
        *reinterpret_cast<float4*>(op + 4) = o1;
    }
}

// ---------------------------------------------------------------------------
extern "C" void kernel_launch(void* const* d_in, const int* in_sizes, int n_in,
                              void* d_out, int out_size) {
    const float* h   = (const float*)d_in[0];
    const int*   adj = (const int*)  d_in[1];
    const float* Ws  = (const float*)d_in[2];
    const float* Wt  = (const float*)d_in[3];
    const float* Wc  = (const float*)d_in[4];
    float* out = (float*)d_out;

    proj_kernel<<<B_ * N_ / 4, 256>>>(h, Ws, Wt, Wc);

    const int smemBytes = (3 * 64 * QS + 64 * DO_) * (int)sizeof(float);  // 84992
    cudaFuncSetAttribute(attn_kernel,
                         cudaFuncAttributeMaxDynamicSharedMemorySize, smemBytes);
    dim3 grid(N_ / BM, B_);
    attn_kernel<<<grid, 256, smemBytes>>>(adj, out);
}

// round 5
// speedup vs baseline: 2.7747x; 2.7747x over previous
#include <cuda_runtime.h>
#include <cuda_bf16.h>
#include <cstdint>

#define B_   4
#define N_   4096
#define DIN_ 128
#define H_   64
#define DO_  128
#define BM   128
#define BN   64
#define NTILES 64
#define NWRD 128

// smem layout (bytes). Q rows padded to 144B, V rows to 272B (conflict-free ldmatrix)
#define OFF_QH  0
#define OFF_QL  18432
#define OFF_BUF 36864
#define BUFSZ   53248
#define KH_O    0
#define KL_O    9216
#define VH_O    18432
#define VL_O    35840
#define SMEM_ALLOC 143360

__device__ __nv_bfloat16 g_Qh[B_*N_*H_], g_Ql[B_*N_*H_];
__device__ __nv_bfloat16 g_Kh[B_*N_*H_], g_Kl[B_*N_*H_];
__device__ __nv_bfloat16 g_Vh[B_*N_*DO_], g_Vl[B_*N_*DO_];
__device__ unsigned g_adjb[N_*NWRD];

__device__ __forceinline__ uint32_t smem_u32(const void* p) {
    uint32_t a;
    asm("{ .reg .u64 t; cvta.to.shared.u64 t, %1; cvt.u32.u64 %0, t; }" : "=r"(a) : "l"(p));
    return a;
}
__device__ __forceinline__ void mma16816(float* c, const uint32_t* a, const uint32_t* b) {
    asm volatile("mma.sync.aligned.m16n8k16.row.col.f32.bf16.bf16.f32 "
        "{%0,%1,%2,%3}, {%4,%5,%6,%7}, {%8,%9}, {%0,%1,%2,%3};"
        : "+f"(c[0]), "+f"(c[1]), "+f"(c[2]), "+f"(c[3])
        : "r"(a[0]), "r"(a[1]), "r"(a[2]), "r"(a[3]), "r"(b[0]), "r"(b[1]));
}
__device__ __forceinline__ void ldsm_x2(uint32_t* r, uint32_t a) {
    asm volatile("ldmatrix.sync.aligned.m8n8.x2.shared.b16 {%0,%1}, [%2];"
        : "=r"(r[0]), "=r"(r[1]) : "r"(a));
}
__device__ __forceinline__ void ldsm_x2_t(uint32_t* r, uint32_t a) {
    asm volatile("ldmatrix.sync.aligned.m8n8.x2.trans.shared.b16 {%0,%1}, [%2];"
        : "=r"(r[0]), "=r"(r[1]) : "r"(a));
}
__device__ __forceinline__ void ldsm_x4(uint32_t* r, uint32_t a) {
    asm volatile("ldmatrix.sync.aligned.m8n8.x4.shared.b16 {%0,%1,%2,%3}, [%4];"
        : "=r"(r[0]), "=r"(r[1]), "=r"(r[2]), "=r"(r[3]) : "r"(a));
}
__device__ __forceinline__ void cpa16(uint32_t dst, const void* src) {
    asm volatile("cp.async.cg.shared.global [%0], [%1], 16;" :: "r"(dst), "l"(src));
}
#define CP_COMMIT() asm volatile("cp.async.commit_group;" ::: "memory")
#define CP_WAIT(n)  asm volatile("cp.async.wait_group %0;" :: "n"(n) : "memory")

__device__ __forceinline__ uint32_t packbf2(__nv_bfloat16 a, __nv_bfloat16 b) {
    __nv_bfloat162 t = __halves2bfloat162(a, b);
    return *(uint32_t*)&t;
}

// ============================ prep kernels ============================
__global__ __launch_bounds__(256) void pack_adj_kernel(const int* __restrict__ adj) {
    int gw = (blockIdx.x * 256 + threadIdx.x) >> 5;
    int lane = threadIdx.x & 31;
    int v = adj[(size_t)gw * 32 + lane];
    unsigned m = __ballot_sync(0xffffffffu, v > 0);
    if (lane == 0) g_adjb[gw] = m;
}

__global__ __launch_bounds__(256) void proj_kernel(
    const float* __restrict__ h, const float* __restrict__ Ws,
    const float* __restrict__ Wt, const float* __restrict__ Wc) {
    __shared__ float sh[4][DIN_];
    const int row0 = blockIdx.x * 4;
    const int tid = threadIdx.x;
    for (int i = tid; i < 4 * DIN_; i += 256)
        sh[i >> 7][i & 127] = h[(size_t)row0 * DIN_ + i];
    __syncthreads();

    const int c = tid;
    const float* W; int col, stride;
    if (c < 64)       { W = Ws; col = c;       stride = H_;  }
    else if (c < 128) { W = Wt; col = c - 64;  stride = H_;  }
    else              { W = Wc; col = c - 128; stride = DO_; }

    float a[4] = {0.f, 0.f, 0.f, 0.f};
    const float* wp = W + col;
    #pragma unroll 16
    for (int k = 0; k < DIN_; ++k) {
        float w = wp[k * stride];
        a[0] = fmaf(sh[0][k], w, a[0]);
        a[1] = fmaf(sh[1][k], w, a[1]);
        a[2] = fmaf(sh[2][k], w, a[2]);
        a[3] = fmaf(sh[3][k], w, a[3]);
    }
    #pragma unroll
    for (int i = 0; i < 4; ++i) {
        int rn = row0 + i;
        __nv_bfloat16 hi = __float2bfloat16(a[i]);
        __nv_bfloat16 lo = __float2bfloat16(a[i] - __bfloat162float(hi));
        if (c < 64)       { g_Qh[(size_t)rn*H_  + col] = hi; g_Ql[(size_t)rn*H_  + col] = lo; }
        else if (c < 128) { g_Kh[(size_t)rn*H_  + col] = hi; g_Kl[(size_t)rn*H_  + col] = lo; }
        else              { g_Vh[(size_t)rn*DO_ + col] = hi; g_Vl[(size_t)rn*DO_ + col] = lo; }
    }
}

// ============================ attention ============================
__device__ __forceinline__ void load_tile_async(
    uint32_t bufb, int tid, const __nv_bfloat16* Kh, const __nv_bfloat16* Kl,
    const __nv_bfloat16* Vh, const __nv_bfloat16* Vl) {
    #pragma unroll
    for (int i = tid; i < 512; i += 256) {     // K hi/lo: 64 rows x 8 x 16B
        int rr = i >> 3, x = i & 7;
        cpa16(bufb + KH_O + rr*144 + x*16, Kh + rr*H_ + x*8);
        cpa16(bufb + KL_O + rr*144 + x*16, Kl + rr*H_ + x*8);
    }
    #pragma unroll
    for (int i = tid; i < 1024; i += 256) {    // V hi/lo: 64 rows x 16 x 16B
        int rr = i >> 4, x = i & 15;
        cpa16(bufb + VH_O + rr*272 + x*16, Vh + rr*DO_ + x*8);
        cpa16(bufb + VL_O + rr*272 + x*16, Vl + rr*DO_ + x*8);
    }
}

__global__ __launch_bounds__(256, 1) void attn_kernel(float* __restrict__ out) {
    extern __shared__ char sm[];
    const uint32_t sbase = smem_u32(sm);
    const int tid = threadIdx.x, wm = tid >> 5, lane = tid & 31;
    const int bi = blockIdx.y, row0 = blockIdx.x * BM;

    const __nv_bfloat16* Khb = g_Kh + (size_t)bi * N_ * H_;
    const __nv_bfloat16* Klb = g_Kl + (size_t)bi * N_ * H_;
    const __nv_bfloat16* Vhb = g_Vh + (size_t)bi * N_ * DO_;
    const __nv_bfloat16* Vlb = g_Vl + (size_t)bi * N_ * DO_;

    // stage Q (padded rows), prefetch tile 0
    {
        const __nv_bfloat16* Qh = g_Qh + ((size_t)bi * N_ + row0) * H_;
        const __nv_bfloat16* Ql = g_Ql + ((size_t)bi * N_ + row0) * H_;
        #pragma unroll
        for (int i = tid; i < BM * 8; i += 256) {
            int rr = i >> 3, x = i & 7;
            *(uint4*)(sm + OFF_QH + rr*144 + x*16) = *(const uint4*)(Qh + rr*H_ + x*8);
            *(uint4*)(sm + OFF_QL + rr*144 + x*16) = *(const uint4*)(Ql + rr*H_ + x*8);
        }
    }
    load_tile_async(sbase + OFF_BUF, tid, Khb, Klb, Vhb, Vlb);
    CP_COMMIT();
    __syncthreads();

    // Q A-fragments (persistent in registers)
    uint32_t qh[4][4], ql[4][4];
    {
        int qrow = wm * 16 + (lane & 15);
        uint32_t base = sbase + qrow * 144 + ((lane >> 4) & 1) * 16;
        #pragma unroll
        for (int ks = 0; ks < 4; ++ks) {
            ldsm_x4(qh[ks], base + OFF_QH + ks * 32);
            ldsm_x4(ql[ks], base + OFF_QL + ks * 32);
        }
    }

    float o[16][4];
    #pragma unroll
    for (int d = 0; d < 16; ++d) { o[d][0]=0.f; o[d][1]=0.f; o[d][2]=0.f; o[d][3]=0.f; }
    float m0 = -1e30f, m1 = -1e30f, l0 = 0.f, l1 = 0.f;

    const int r0 = lane >> 2;
    const unsigned* adjr0 = g_adjb + (size_t)(row0 + wm*16 + r0) * NWRD;
    const unsigned* adjr1 = adjr0 + 8 * NWRD;

    for (int jb = 0; jb < NTILES; ++jb) {
        const uint32_t buf = sbase + OFF_BUF + (jb & 1) * BUFSZ;
        if (jb + 1 < NTILES) {
            int c1 = (jb + 1) * BN;
            load_tile_async(sbase + OFF_BUF + ((jb+1)&1)*BUFSZ, tid,
                            Khb + (size_t)c1*H_, Klb + (size_t)c1*H_,
                            Vhb + (size_t)c1*DO_, Vlb + (size_t)c1*DO_);
            CP_COMMIT();
            CP_WAIT(1);
        } else {
            CP_WAIT(0);
        }
        __syncthreads();

        // ---- S = Q K^T (3 compensated passes) ----
        float s[8][4];
        #pragma unroll
        for (int nt = 0; nt < 8; ++nt) { s[nt][0]=0.f; s[nt][1]=0.f; s[nt][2]=0.f; s[nt][3]=0.f; }
        #pragma unroll
        for (int ks = 0; ks < 4; ++ks) {
            #pragma unroll
            for (int nt = 0; nt < 8; ++nt) {
                uint32_t ka = buf + (nt*8 + (lane&7))*144 + ks*32 + ((lane>>3)&1)*16;
                uint32_t bh[2], bl[2];
                ldsm_x2(bh, ka + KH_O);
                ldsm_x2(bl, ka + KL_O);
                mma16816(s[nt], qh[ks], bh);
                mma16816(s[nt], qh[ks], bl);
                mma16816(s[nt], ql[ks], bh);
            }
        }

        // ---- masks + online softmax (registers + shfl only) ----
        unsigned a00 = adjr0[jb*2], a01 = adjr0[jb*2+1];
        unsigned a10 = adjr1[jb*2], a11 = adjr1[jb*2+1];
        float lm0 = -1e30f, lm1 = -1e30f;
        #pragma unroll
        for (int nt = 0; nt < 8; ++nt) {
            unsigned w0 = (nt < 4) ? a00 : a01;
            unsigned w1 = (nt < 4) ? a10 : a11;
            int bb = (nt & 3) * 8 + (lane & 3) * 2;
            if ((w0 >> bb) & 1u)     lm0 = fmaxf(lm0, s[nt][0]);
            if ((w0 >> (bb+1)) & 1u) lm0 = fmaxf(lm0, s[nt][1]);
            if ((w1 >> bb) & 1u)     lm1 = fmaxf(lm1, s[nt][2]);
            if ((w1 >> (bb+1)) & 1u) lm1 = fmaxf(lm1, s[nt][3]);
        }
        lm0 = fmaxf(lm0, __shfl_xor_sync(0xffffffffu, lm0, 1));
        lm0 = fmaxf(lm0, __shfl_xor_sync(0xffffffffu, lm0, 2));
        lm1 = fmaxf(lm1, __shfl_xor_sync(0xffffffffu, lm1, 1));
        lm1 = fmaxf(lm1, __shfl_xor_sync(0xffffffffu, lm1, 2));
        float mn0 = fmaxf(m0, lm0), mn1 = fmaxf(m1, lm1);
        float sc0 = __expf(m0 - mn0), sc1 = __expf(m1 - mn1);
        m0 = mn0; m1 = mn1; l0 *= sc0; l1 *= sc1;
        #pragma unroll
        for (int d = 0; d < 16; ++d) {
            o[d][0] *= sc0; o[d][1] *= sc0; o[d][2] *= sc1; o[d][3] *= sc1;
        }

        // ---- P = exp(S - m) masked, split hi/lo, packed as A-fragments ----
        uint32_t ph[4][4], pl[4][4];
        #pragma unroll
        for (int kk = 0; kk < 4; ++kk) {
            #pragma unroll
            for (int h2 = 0; h2 < 2; ++h2) {
                int nt = kk * 2 + h2;
                unsigned w0 = (nt < 4) ? a00 : a01;
                unsigned w1 = (nt < 4) ? a10 : a11;
                int bb = (nt & 3) * 8 + (lane & 3) * 2;
                float p0 = ((w0 >> bb) & 1u)     ? __expf(s[nt][0] - mn0) : 0.f;
                float p1 = ((w0 >> (bb+1)) & 1u) ? __expf(s[nt][1] - mn0) : 0.f;
                float p2 = ((w1 >> bb) & 1u)     ? __expf(s[nt][2] - mn1) : 0.f;
                float p3 = ((w1 >> (bb+1)) & 1u) ? __expf(s[nt][3] - mn1) : 0.f;
                l0 += p0 + p1;  l1 += p2 + p3;
                __nv_bfloat16 h0 = __float2bfloat16(p0), h1 = __float2bfloat16(p1);
                __nv_bfloat16 h2b = __float2bfloat16(p2), h3 = __float2bfloat16(p3);
                ph[kk][h2*2+0] = packbf2(h0, h1);
                ph[kk][h2*2+1] = packbf2(h2b, h3);
                pl[kk][h2*2+0] = packbf2(__float2bfloat16(p0 - __bfloat162float(h0)),
                                         __float2bfloat16(p1 - __bfloat162float(h1)));
                pl[kk][h2*2+1] = packbf2(__float2bfloat16(p2 - __bfloat162float(h2b)),
                                         __float2bfloat16(p3 - __bfloat162float(h3)));
            }
        }

        // ---- O += P V (3 compensated passes) ----
        #pragma unroll
        for (int dt = 0; dt < 16; ++dt) {
            #pragma unroll
            for (int kk = 0; kk < 4; ++kk) {
                uint32_t va = buf + (kk*16 + (lane&15))*272 + dt*16;
                uint32_t vh[2], vl[2];
                ldsm_x2_t(vh, va + VH_O);
                ldsm_x2_t(vl, va + VL_O);
                mma16816(o[dt], ph[kk], vh);
                mma16816(o[dt], ph[kk], vl);
                mma16816(o[dt], pl[kk], vh);
            }
        }
        __syncthreads();  // all reads of buf done before it is refilled
    }

    // ---- epilogue ----
    l0 += __shfl_xor_sync(0xffffffffu, l0, 1);
    l0 += __shfl_xor_sync(0xffffffffu, l0, 2);
    l1 += __shfl_xor_sync(0xffffffffu, l1, 1);
    l1 += __shfl_xor_sync(0xffffffffu, l1, 2);
    float inv0 = 1.0f / l0, inv1 = 1.0f / l1;
    int gr0 = row0 + wm * 16 + r0;
    float* ob = out + ((size_t)bi * N_ + gr0) * DO_ + (lane & 3) * 2;
    #pragma unroll
    for (int dt = 0; dt < 16; ++dt) {
        float2 v0 = make_float2(o[dt][0] * inv0, o[dt][1] * inv0);
        float2 v1 = make_float2(o[dt][2] * inv1, o[dt][3] * inv1);
        *(float2*)(ob + dt * 8)            = v0;
        *(float2*)(ob + 8 * DO_ + dt * 8)  = v1;
    }
}

// ---------------------------------------------------------------------------
extern "C" void kernel_launch(void* const* d_in, const int* in_sizes, int n_in,
                              void* d_out, int out_size) {
    const float* h   = (const float*)d_in[0];
    const int*   adj = (const int*)  d_in[1];
    const float* Ws  = (const float*)d_in[2];
    const float* Wt  = (const float*)d_in[3];
    const float* Wc  = (const float*)d_in[4];
    float* out = (float*)d_out;

    pack_adj_kernel<<<N_ * NWRD / 8, 256>>>(adj);
    proj_kernel<<<B_ * N_ / 4, 256>>>(h, Ws, Wt, Wc);

    cudaFuncSetAttribute(attn_kernel,
                         cudaFuncAttributeMaxDynamicSharedMemorySize, SMEM_ALLOC);
    dim3 grid(N_ / BM, B_);
    attn_kernel<<<grid, 256, SMEM_ALLOC>>>(out);
}

// round 6
// speedup vs baseline: 3.8924x; 1.4028x over previous
#include <cuda_runtime.h>
#include <cuda_fp16.h>
#include <cstdint>

#define B_   4
#define N_   4096
#define DIN_ 128
#define H_   64
#define DO_  128
#define BM   128
#define BN   64
#define NTILES 64
#define NWRD 128
#define PACK_BLKS 16384

// smem layout (bytes). Q/K rows padded to 144B, V rows to 272B
#define OFF_QH  0
#define OFF_QL  18432
#define OFF_BUF 36864
#define BUFSZ   35840
#define KH_O    0
#define KL_O    9216
#define VH_O    18432
#define SMEM_ALLOC 108544

__device__ __half g_Qh[B_*N_*H_], g_Ql[B_*N_*H_];
__device__ __half g_Kh[B_*N_*H_], g_Kl[B_*N_*H_];
__device__ __half g_Vh[B_*N_*DO_];
__device__ unsigned g_adjb[N_*NWRD];

__device__ __forceinline__ uint32_t smem_u32(const void* p) {
    uint32_t a;
    asm("{ .reg .u64 t; cvta.to.shared.u64 t, %1; cvt.u32.u64 %0, t; }" : "=r"(a) : "l"(p));
    return a;
}
__device__ __forceinline__ void mma16816(float* c, const uint32_t* a, const uint32_t* b) {
    asm volatile("mma.sync.aligned.m16n8k16.row.col.f32.f16.f16.f32 "
        "{%0,%1,%2,%3}, {%4,%5,%6,%7}, {%8,%9}, {%0,%1,%2,%3};"
        : "+f"(c[0]), "+f"(c[1]), "+f"(c[2]), "+f"(c[3])
        : "r"(a[0]), "r"(a[1]), "r"(a[2]), "r"(a[3]), "r"(b[0]), "r"(b[1]));
}
__device__ __forceinline__ void ldsm_x4(uint32_t* r, uint32_t a) {
    asm volatile("ldmatrix.sync.aligned.m8n8.x4.shared.b16 {%0,%1,%2,%3}, [%4];"
        : "=r"(r[0]), "=r"(r[1]), "=r"(r[2]), "=r"(r[3]) : "r"(a));
}
__device__ __forceinline__ void ldsm_x4_t(uint32_t* r, uint32_t a) {
    asm volatile("ldmatrix.sync.aligned.m8n8.x4.trans.shared.b16 {%0,%1,%2,%3}, [%4];"
        : "=r"(r[0]), "=r"(r[1]), "=r"(r[2]), "=r"(r[3]) : "r"(a));
}
__device__ __forceinline__ void cpa16(uint32_t dst, const void* src) {
    asm volatile("cp.async.cg.shared.global [%0], [%1], 16;" :: "r"(dst), "l"(src));
}
#define CP_COMMIT() asm volatile("cp.async.commit_group;" ::: "memory")
#define CP_WAIT(n)  asm volatile("cp.async.wait_group %0;" :: "n"(n) : "memory")

__device__ __forceinline__ uint32_t packh2(float a, float b) {
    __half2 t = __floats2half2_rn(a, b);
    return *(uint32_t*)&t;
}

// ============== fused prep: adj bit-pack (DRAM-bound) + projections ==============
__global__ __launch_bounds__(256) void prep_kernel(
    const float* __restrict__ h, const int* __restrict__ adj,
    const float* __restrict__ Ws, const float* __restrict__ Wt,
    const float* __restrict__ Wc) {
    __shared__ float sh[4][DIN_];
    const int tid = threadIdx.x;

    if (blockIdx.x < PACK_BLKS) {
        // ---- pack: 1024 ints per block, int4 per thread, nibble-shfl assembly ----
        int t = blockIdx.x * 256 + tid;
        int lane = tid & 31;
        int4 v = *(const int4*)(adj + (size_t)t * 4);
        unsigned nib = (unsigned)(v.x > 0) | ((unsigned)(v.y > 0) << 1) |
                       ((unsigned)(v.z > 0) << 2) | ((unsigned)(v.w > 0) << 3);
        unsigned x = nib << ((lane & 7) * 4);
        x |= __shfl_xor_sync(0xffffffffu, x, 1);
        x |= __shfl_xor_sync(0xffffffffu, x, 2);
        x |= __shfl_xor_sync(0xffffffffu, x, 4);
        if ((lane & 7) == 0) g_adjb[(size_t)(t >> 5) * 4 + (lane >> 3)] = x;
        return;
    }

    // ---- proj: Q/K fp16 hi+lo, V fp16 ----
    const int row0 = (blockIdx.x - PACK_BLKS) * 4;
    for (int i = tid; i < 4 * DIN_; i += 256)
        sh[i >> 7][i & 127] = h[(size_t)row0 * DIN_ + i];
    __syncthreads();

    const int c = tid;
    const float* W; int col, stride;
    if (c < 64)       { W = Ws; col = c;       stride = H_;  }
    else if (c < 128) { W = Wt; col = c - 64;  stride = H_;  }
    else              { W = Wc; col = c - 128; stride = DO_; }

    float a[4] = {0.f, 0.f, 0.f, 0.f};
    const float* wp = W + col;
    #pragma unroll 16
    for (int k = 0; k < DIN_; ++k) {
        float w = wp[k * stride];
        a[0] = fmaf(sh[0][k], w, a[0]);
        a[1] = fmaf(sh[1][k], w, a[1]);
        a[2] = fmaf(sh[2][k], w, a[2]);
        a[3] = fmaf(sh[3][k], w, a[3]);
    }
    #pragma unroll
    for (int i = 0; i < 4; ++i) {
        int rn = row0 + i;
        if (c < 192) {
            __half hi = __float2half_rn(a[i]);
            __half lo = __float2half_rn(a[i] - __half2float(hi));
            if (c < 64)  { g_Qh[(size_t)rn*H_ + col] = hi; g_Ql[(size_t)rn*H_ + col] = lo; }
            else if (c < 128) { g_Kh[(size_t)rn*H_ + col] = hi; g_Kl[(size_t)rn*H_ + col] = lo; }
            else g_Vh[(size_t)rn*DO_ + col] = __float2half_rn(a[i]);
        } else {
            g_Vh[(size_t)rn*DO_ + col] = __float2half_rn(a[i]);
        }
    }
}

// ============================ attention ============================
__device__ __forceinline__ void load_tile_async(
    uint32_t bufb, int tid, const __half* Kh, const __half* Kl, const __half* Vh) {
    #pragma unroll
    for (int i = tid; i < 512; i += 256) {     // K hi/lo: 64 rows x 8 x 16B
        int rr = i >> 3, x = i & 7;
        cpa16(bufb + KH_O + rr*144 + x*16, Kh + rr*H_ + x*8);
        cpa16(bufb + KL_O + rr*144 + x*16, Kl + rr*H_ + x*8);
    }
    #pragma unroll
    for (int i = tid; i < 1024; i += 256) {    // V: 64 rows x 16 x 16B
        int rr = i >> 4, x = i & 15;
        cpa16(bufb + VH_O + rr*272 + x*16, Vh + rr*DO_ + x*8);
    }
}

__global__ __launch_bounds__(256, 1) void attn_kernel(float* __restrict__ out) {
    extern __shared__ char sm[];
    const uint32_t sbase = smem_u32(sm);
    const int tid = threadIdx.x, wm = tid >> 5, lane = tid & 31;
    const int bi = blockIdx.y, row0 = blockIdx.x * BM;

    const __half* Khb = g_Kh + (size_t)bi * N_ * H_;
    const __half* Klb = g_Kl + (size_t)bi * N_ * H_;
    const __half* Vhb = g_Vh + (size_t)bi * N_ * DO_;

    {
        const __half* Qh = g_Qh + ((size_t)bi * N_ + row0) * H_;
        const __half* Ql = g_Ql + ((size_t)bi * N_ + row0) * H_;
        #pragma unroll
        for (int i = tid; i < BM * 8; i += 256) {
            int rr = i >> 3, x = i & 7;
            *(uint4*)(sm + OFF_QH + rr*144 + x*16) = *(const uint4*)(Qh + rr*H_ + x*8);
            *(uint4*)(sm + OFF_QL + rr*144 + x*16) = *(const uint4*)(Ql + rr*H_ + x*8);
        }
    }
    load_tile_async(sbase + OFF_BUF, tid, Khb, Klb, Vhb);
    CP_COMMIT();
    __syncthreads();

    // Q A-fragments (persistent)
    uint32_t qh[4][4], ql[4][4];
    {
        int qrow = wm * 16 + (lane & 15);
        uint32_t base = sbase + qrow * 144 + ((lane >> 4) & 1) * 16;
        #pragma unroll
        for (int ks = 0; ks < 4; ++ks) {
            ldsm_x4(qh[ks], base + OFF_QH + ks * 32);
            ldsm_x4(ql[ks], base + OFF_QL + ks * 32);
        }
    }

    float o[16][4];
    #pragma unroll
    for (int d = 0; d < 16; ++d) { o[d][0]=0.f; o[d][1]=0.f; o[d][2]=0.f; o[d][3]=0.f; }
    float m0 = -1e30f, m1 = -1e30f, l0 = 0.f, l1 = 0.f;

    const int r0 = lane >> 2;
    const unsigned* adjr0 = g_adjb + (size_t)(row0 + wm*16 + r0) * NWRD;
    const unsigned* adjr1 = adjr0 + 8 * NWRD;

    for (int jb = 0; jb < NTILES; ++jb) {
        const uint32_t buf = sbase + OFF_BUF + (jb & 1) * BUFSZ;
        if (jb + 1 < NTILES) {
            int c1 = (jb + 1) * BN;
            load_tile_async(sbase + OFF_BUF + ((jb+1)&1)*BUFSZ, tid,
                            Khb + (size_t)c1*H_, Klb + (size_t)c1*H_, Vhb + (size_t)c1*DO_);
            CP_COMMIT();
            CP_WAIT(1);
        } else {
            CP_WAIT(0);
        }
        __syncthreads();

        // ---- S = Q K^T: 3 compensated fp16 passes, combined hi/lo ldsm ----
        float s[8][4];
        #pragma unroll
        for (int nt = 0; nt < 8; ++nt) { s[nt][0]=0.f; s[nt][1]=0.f; s[nt][2]=0.f; s[nt][3]=0.f; }
        #pragma unroll
        for (int ks = 0; ks < 4; ++ks) {
            #pragma unroll
            for (int nt = 0; nt < 8; ++nt) {
                uint32_t ka = buf + ((lane & 16) ? KL_O : KH_O)
                            + (nt*8 + (lane&7))*144 + ks*32 + ((lane>>3)&1)*16;
                uint32_t kb[4];                 // [0..1]=Kh frag, [2..3]=Kl frag
                ldsm_x4(kb, ka);
                mma16816(s[nt], qh[ks], kb);
                mma16816(s[nt], qh[ks], kb + 2);
                mma16816(s[nt], ql[ks], kb);
            }
        }

        // ---- masks + online softmax ----
        unsigned a00 = adjr0[jb*2], a01 = adjr0[jb*2+1];
        unsigned a10 = adjr1[jb*2], a11 = adjr1[jb*2+1];
        float lm0 = -1e30f, lm1 = -1e30f;
        #pragma unroll
        for (int nt = 0; nt < 8; ++nt) {
            unsigned w0 = (nt < 4) ? a00 : a01;
            unsigned w1 = (nt < 4) ? a10 : a11;
            int bb = (nt & 3) * 8 + (lane & 3) * 2;
            if ((w0 >> bb) & 1u)     lm0 = fmaxf(lm0, s[nt][0]);
            if ((w0 >> (bb+1)) & 1u) lm0 = fmaxf(lm0, s[nt][1]);
            if ((w1 >> bb) & 1u)     lm1 = fmaxf(lm1, s[nt][2]);
            if ((w1 >> (bb+1)) & 1u) lm1 = fmaxf(lm1, s[nt][3]);
        }
        lm0 = fmaxf(lm0, __shfl_xor_sync(0xffffffffu, lm0, 1));
        lm0 = fmaxf(lm0, __shfl_xor_sync(0xffffffffu, lm0, 2));
        lm1 = fmaxf(lm1, __shfl_xor_sync(0xffffffffu, lm1, 1));
        lm1 = fmaxf(lm1, __shfl_xor_sync(0xffffffffu, lm1, 2));
        float mn0 = fmaxf(m0, lm0), mn1 = fmaxf(m1, lm1);
        float sc0 = __expf(m0 - mn0), sc1 = __expf(m1 - mn1);
        m0 = mn0; m1 = mn1; l0 *= sc0; l1 *= sc1;
        #pragma unroll
        for (int d = 0; d < 16; ++d) {
            o[d][0] *= sc0; o[d][1] *= sc0; o[d][2] *= sc1; o[d][3] *= sc1;
        }

        // ---- P = exp(S - m) masked -> fp16 A-fragments (single precision pass) ----
        uint32_t ph[4][4];
        #pragma unroll
        for (int kk = 0; kk < 4; ++kk) {
            #pragma unroll
            for (int h2 = 0; h2 < 2; ++h2) {
                int nt = kk * 2 + h2;
                unsigned w0 = (nt < 4) ? a00 : a01;
                unsigned w1 = (nt < 4) ? a10 : a11;
                int bb = (nt & 3) * 8 + (lane & 3) * 2;
                float p0 = ((w0 >> bb) & 1u)     ? __expf(s[nt][0] - mn0) : 0.f;
                float p1 = ((w0 >> (bb+1)) & 1u) ? __expf(s[nt][1] - mn0) : 0.f;
                float p2 = ((w1 >> bb) & 1u)     ? __expf(s[nt][2] - mn1) : 0.f;
                float p3 = ((w1 >> (bb+1)) & 1u) ? __expf(s[nt][3] - mn1) : 0.f;
                l0 += p0 + p1;  l1 += p2 + p3;
                ph[kk][h2*2+0] = packh2(p0, p1);
                ph[kk][h2*2+1] = packh2(p2, p3);
            }
        }

        // ---- O += P V: single fp16 pass, x4.trans loads two dt chunks ----
        #pragma unroll
        for (int dt = 0; dt < 16; dt += 2) {
            #pragma unroll
            for (int kk = 0; kk < 4; ++kk) {
                uint32_t va = buf + VH_O + (kk*16 + (lane&15))*272
                            + dt*16 + ((lane>>4)&1)*16;
                uint32_t vv[4];                 // [0..1]=dt frag, [2..3]=dt+1 frag
                ldsm_x4_t(vv, va);
                mma16816(o[dt],     ph[kk], vv);
                mma16816(o[dt + 1], ph[kk], vv + 2);
            }
        }
        __syncthreads();
    }

    // ---- epilogue ----
    l0 += __shfl_xor_sync(0xffffffffu, l0, 1);
    l0 += __shfl_xor_sync(0xffffffffu, l0, 2);
    l1 += __shfl_xor_sync(0xffffffffu, l1, 1);
    l1 += __shfl_xor_sync(0xffffffffu, l1, 2);
    float inv0 = 1.0f / l0, inv1 = 1.0f / l1;
    int gr0 = row0 + wm * 16 + r0;
    float* ob = out + ((size_t)bi * N_ + gr0) * DO_ + (lane & 3) * 2;
    #pragma unroll
    for (int dt = 0; dt < 16; ++dt) {
        float2 v0 = make_float2(o[dt][0] * inv0, o[dt][1] * inv0);
        float2 v1 = make_float2(o[dt][2] * inv1, o[dt][3] * inv1);
        *(float2*)(ob + dt * 8)            = v0;
        *(float2*)(ob + 8 * DO_ + dt * 8)  = v1;
    }
}

// ---------------------------------------------------------------------------
extern "C" void kernel_launch(void* const* d_in, const int* in_sizes, int n_in,
                              void* d_out, int out_size) {
    const float* h   = (const float*)d_in[0];
    const int*   adj = (const int*)  d_in[1];
    const float* Ws  = (const float*)d_in[2];
    const float* Wt  = (const float*)d_in[3];
    const float* Wc  = (const float*)d_in[4];
    float* out = (float*)d_out;

    prep_kernel<<<PACK_BLKS + B_ * N_ / 4, 256>>>(h, adj, Ws, Wt, Wc);

    cudaFuncSetAttribute(attn_kernel,
                         cudaFuncAttributeMaxDynamicSharedMemorySize, SMEM_ALLOC);
    dim3 grid(N_ / BM, B_);
    attn_kernel<<<grid, 256, SMEM_ALLOC>>>(out);
}

// round 7
// speedup vs baseline: 4.3015x; 1.1051x over previous
#include <cuda_runtime.h>
#include <cuda_fp16.h>
#include <cstdint>

#define B_   4
#define N_   4096
#define DIN_ 128
#define H_   64
#define DO_  128
#define BM   64
#define BN   64
#define NTILES 64
#define NWRD 128
#define PACK_BLKS 2048
#define LOG2E 1.4426950408889634f

// smem layout (bytes). Q/K rows padded to 144B, V rows to 272B
#define OFF_QH  0
#define OFF_QL  9216
#define OFF_BUF 18432
#define BUFSZ   35840
#define KH_O    0
#define KL_O    9216
#define VH_O    18432
#define SMEM_ALLOC 90112

__device__ __half g_Qh[B_*N_*H_], g_Ql[B_*N_*H_];
__device__ __half g_Kh[B_*N_*H_], g_Kl[B_*N_*H_];
__device__ __half g_Vh[B_*N_*DO_];
__device__ unsigned g_adjb[N_*NWRD];

__device__ __forceinline__ uint32_t smem_u32(const void* p) {
    uint32_t a;
    asm("{ .reg .u64 t; cvta.to.shared.u64 t, %1; cvt.u32.u64 %0, t; }" : "=r"(a) : "l"(p));
    return a;
}
__device__ __forceinline__ void mma16816(float* c, const uint32_t* a, const uint32_t* b) {
    asm volatile("mma.sync.aligned.m16n8k16.row.col.f32.f16.f16.f32 "
        "{%0,%1,%2,%3}, {%4,%5,%6,%7}, {%8,%9}, {%0,%1,%2,%3};"
        : "+f"(c[0]), "+f"(c[1]), "+f"(c[2]), "+f"(c[3])
        : "r"(a[0]), "r"(a[1]), "r"(a[2]), "r"(a[3]), "r"(b[0]), "r"(b[1]));
}
__device__ __forceinline__ void ldsm_x4(uint32_t* r, uint32_t a) {
    asm volatile("ldmatrix.sync.aligned.m8n8.x4.shared.b16 {%0,%1,%2,%3}, [%4];"
        : "=r"(r[0]), "=r"(r[1]), "=r"(r[2]), "=r"(r[3]) : "r"(a));
}
__device__ __forceinline__ void ldsm_x4_t(uint32_t* r, uint32_t a) {
    asm volatile("ldmatrix.sync.aligned.m8n8.x4.trans.shared.b16 {%0,%1,%2,%3}, [%4];"
        : "=r"(r[0]), "=r"(r[1]), "=r"(r[2]), "=r"(r[3]) : "r"(a));
}
__device__ __forceinline__ void cpa16(uint32_t dst, const void* src) {
    asm volatile("cp.async.cg.shared.global [%0], [%1], 16;" :: "r"(dst), "l"(src));
}
#define CP_COMMIT() asm volatile("cp.async.commit_group;" ::: "memory")
#define CP_WAIT(n)  asm volatile("cp.async.wait_group %0;" :: "n"(n) : "memory")

__device__ __forceinline__ uint32_t packh2(float a, float b) {
    __half2 t = __floats2half2_rn(a, b);
    return *(uint32_t*)&t;
}

// ============== fused prep: adj bit-pack (MLP=8) + projections ==============
__global__ __launch_bounds__(256) void prep_kernel(
    const float* __restrict__ h, const int* __restrict__ adj,
    const float* __restrict__ Ws, const float* __restrict__ Wt,
    const float* __restrict__ Wc) {
    __shared__ float sh[4][DIN_];
    const int tid = threadIdx.x;

    if (blockIdx.x < PACK_BLKS) {
        // each thread packs 32 consecutive ints -> one bitmask word (8 x LDG.128)
        int w = blockIdx.x * 256 + tid;
        const int4* p = (const int4*)(adj + (size_t)w * 32);
        unsigned word = 0;
        #pragma unroll
        for (int j = 0; j < 8; ++j) {
            int4 v = p[j];
            unsigned nib = (unsigned)(v.x > 0) | ((unsigned)(v.y > 0) << 1) |
                           ((unsigned)(v.z > 0) << 2) | ((unsigned)(v.w > 0) << 3);
            word |= nib << (j * 4);
        }
        g_adjb[w] = word;
        return;
    }

    // ---- proj: Q/K fp16 hi+lo, V fp16 ----
    const int row0 = (blockIdx.x - PACK_BLKS) * 4;
    for (int i = tid; i < 4 * DIN_; i += 256)
        sh[i >> 7][i & 127] = h[(size_t)row0 * DIN_ + i];
    __syncthreads();

    const int c = tid;
    const float* W; int col, stride;
    if (c < 64)       { W = Ws; col = c;       stride = H_;  }
    else if (c < 128) { W = Wt; col = c - 64;  stride = H_;  }
    else              { W = Wc; col = c - 128; stride = DO_; }

    float a[4] = {0.f, 0.f, 0.f, 0.f};
    const float* wp = W + col;
    #pragma unroll 16
    for (int k = 0; k < DIN_; ++k) {
        float w = wp[k * stride];
        a[0] = fmaf(sh[0][k], w, a[0]);
        a[1] = fmaf(sh[1][k], w, a[1]);
        a[2] = fmaf(sh[2][k], w, a[2]);
        a[3] = fmaf(sh[3][k], w, a[3]);
    }
    #pragma unroll
    for (int i = 0; i < 4; ++i) {
        int rn = row0 + i;
        if (c < 128) {
            __half hi = __float2half_rn(a[i]);
            __half lo = __float2half_rn(a[i] - __half2float(hi));
            if (c < 64) { g_Qh[(size_t)rn*H_ + col] = hi; g_Ql[(size_t)rn*H_ + col] = lo; }
            else        { g_Kh[(size_t)rn*H_ + col] = hi; g_Kl[(size_t)rn*H_ + col] = lo; }
        } else {
            g_Vh[(size_t)rn*DO_ + col] = __float2half_rn(a[i]);
        }
    }
}

// ============================ attention ============================
__device__ __forceinline__ void load_tile_async(
    uint32_t bufb, int tid, const __half* Kh, const __half* Kl, const __half* Vh) {
    #pragma unroll
    for (int i = tid; i < 512; i += 128) {     // K hi/lo: 64 rows x 8 x 16B
        int rr = i >> 3, x = i & 7;
        cpa16(bufb + KH_O + rr*144 + x*16, Kh + rr*H_ + x*8);
        cpa16(bufb + KL_O + rr*144 + x*16, Kl + rr*H_ + x*8);
    }
    #pragma unroll
    for (int i = tid; i < 1024; i += 128) {    // V: 64 rows x 16 x 16B
        int rr = i >> 4, x = i & 15;
        cpa16(bufb + VH_O + rr*272 + x*16, Vh + rr*DO_ + x*8);
    }
}

__global__ __launch_bounds__(128, 2) void attn_kernel(float* __restrict__ out) {
    extern __shared__ char sm[];
    const uint32_t sbase = smem_u32(sm);
    const int tid = threadIdx.x, wm = tid >> 5, lane = tid & 31;
    const int bi = blockIdx.y, row0 = blockIdx.x * BM;

    const __half* Khb = g_Kh + (size_t)bi * N_ * H_;
    const __half* Klb = g_Kl + (size_t)bi * N_ * H_;
    const __half* Vhb = g_Vh + (size_t)bi * N_ * DO_;

    {
        const __half* Qh = g_Qh + ((size_t)bi * N_ + row0) * H_;
        const __half* Ql = g_Ql + ((size_t)bi * N_ + row0) * H_;
        #pragma unroll
        for (int i = tid; i < BM * 8; i += 128) {
            int rr = i >> 3, x = i & 7;
            *(uint4*)(sm + OFF_QH + rr*144 + x*16) = *(const uint4*)(Qh + rr*H_ + x*8);
            *(uint4*)(sm + OFF_QL + rr*144 + x*16) = *(const uint4*)(Ql + rr*H_ + x*8);
        }
    }
    load_tile_async(sbase + OFF_BUF, tid, Khb, Klb, Vhb);
    CP_COMMIT();
    __syncthreads();

    // Q A-fragments (persistent)
    uint32_t qh[4][4], ql[4][4];
    {
        int qrow = wm * 16 + (lane & 15);
        uint32_t base = sbase + qrow * 144 + ((lane >> 4) & 1) * 16;
        #pragma unroll
        for (int ks = 0; ks < 4; ++ks) {
            ldsm_x4(qh[ks], base + OFF_QH + ks * 32);
            ldsm_x4(ql[ks], base + OFF_QL + ks * 32);
        }
    }

    float o[16][4];
    #pragma unroll
    for (int d = 0; d < 16; ++d) { o[d][0]=0.f; o[d][1]=0.f; o[d][2]=0.f; o[d][3]=0.f; }
    float m0 = -1e30f, m1 = -1e30f, l0 = 0.f, l1 = 0.f;  // m in log2 domain

    const int r0 = lane >> 2;
    const unsigned* adjr0 = g_adjb + (size_t)(row0 + wm*16 + r0) * NWRD;
    const unsigned* adjr1 = adjr0 + 8 * NWRD;

    for (int jb = 0; jb < NTILES; ++jb) {
        const uint32_t buf = sbase + OFF_BUF + (jb & 1) * BUFSZ;
        if (jb + 1 < NTILES) {
            int c1 = (jb + 1) * BN;
            load_tile_async(sbase + OFF_BUF + ((jb+1)&1)*BUFSZ, tid,
                            Khb + (size_t)c1*H_, Klb + (size_t)c1*H_, Vhb + (size_t)c1*DO_);
            CP_COMMIT();
            CP_WAIT(1);
        } else {
            CP_WAIT(0);
        }
        __syncthreads();

        // ---- S = Q K^T: 3 compensated fp16 passes ----
        float s[8][4];
        #pragma unroll
        for (int nt = 0; nt < 8; ++nt) { s[nt][0]=0.f; s[nt][1]=0.f; s[nt][2]=0.f; s[nt][3]=0.f; }
        #pragma unroll
        for (int ks = 0; ks < 4; ++ks) {
            #pragma unroll
            for (int nt = 0; nt < 8; ++nt) {
                uint32_t ka = buf + ((lane & 16) ? KL_O : KH_O)
                            + (nt*8 + (lane&7))*144 + ks*32 + ((lane>>3)&1)*16;
                uint32_t kb[4];
                ldsm_x4(kb, ka);
                mma16816(s[nt], qh[ks], kb);
                mma16816(s[nt], qh[ks], kb + 2);
                mma16816(s[nt], ql[ks], kb);
            }
        }
        // scale to log2 domain once
        #pragma unroll
        for (int nt = 0; nt < 8; ++nt) {
            s[nt][0] *= LOG2E; s[nt][1] *= LOG2E; s[nt][2] *= LOG2E; s[nt][3] *= LOG2E;
        }

        // ---- masks + online softmax (log2 domain) ----
        unsigned a00 = adjr0[jb*2], a01 = adjr0[jb*2+1];
        unsigned a10 = adjr1[jb*2], a11 = adjr1[jb*2+1];
        float lm0 = -1e30f, lm1 = -1e30f;
        #pragma unroll
        for (int nt = 0; nt < 8; ++nt) {
            unsigned w0 = (nt < 4) ? a00 : a01;
            unsigned w1 = (nt < 4) ? a10 : a11;
            int bb = (nt & 3) * 8 + (lane & 3) * 2;
            if ((w0 >> bb) & 1u)     lm0 = fmaxf(lm0, s[nt][0]);
            if ((w0 >> (bb+1)) & 1u) lm0 = fmaxf(lm0, s[nt][1]);
            if ((w1 >> bb) & 1u)     lm1 = fmaxf(lm1, s[nt][2]);
            if ((w1 >> (bb+1)) & 1u) lm1 = fmaxf(lm1, s[nt][3]);
        }
        lm0 = fmaxf(lm0, __shfl_xor_sync(0xffffffffu, lm0, 1));
        lm0 = fmaxf(lm0, __shfl_xor_sync(0xffffffffu, lm0, 2));
        lm1 = fmaxf(lm1, __shfl_xor_sync(0xffffffffu, lm1, 1));
        lm1 = fmaxf(lm1, __shfl_xor_sync(0xffffffffu, lm1, 2));
        float mn0 = fmaxf(m0, lm0), mn1 = fmaxf(m1, lm1);
        float sc0 = exp2f(m0 - mn0), sc1 = exp2f(m1 - mn1);
        m0 = mn0; m1 = mn1;
        if (sc0 != 1.f || sc1 != 1.f) {
            l0 *= sc0; l1 *= sc1;
            #pragma unroll
            for (int d = 0; d < 16; ++d) {
                o[d][0] *= sc0; o[d][1] *= sc0; o[d][2] *= sc1; o[d][3] *= sc1;
            }
        }

        // ---- P = exp2(S - m) masked -> fp16 A-fragments ----
        uint32_t ph[4][4];
        #pragma unroll
        for (int kk = 0; kk < 4; ++kk) {
            #pragma unroll
            for (int h2 = 0; h2 < 2; ++h2) {
                int nt = kk * 2 + h2;
                unsigned w0 = (nt < 4) ? a00 : a01;
                unsigned w1 = (nt < 4) ? a10 : a11;
                int bb = (nt & 3) * 8 + (lane & 3) * 2;
                float p0 = ((w0 >> bb) & 1u)     ? exp2f(s[nt][0] - mn0) : 0.f;
                float p1 = ((w0 >> (bb+1)) & 1u) ? exp2f(s[nt][1] - mn0) : 0.f;
                float p2 = ((w1 >> bb) & 1u)     ? exp2f(s[nt][2] - mn1) : 0.f;
                float p3 = ((w1 >> (bb+1)) & 1u) ? exp2f(s[nt][3] - mn1) : 0.f;
                l0 += p0 + p1;  l1 += p2 + p3;
                ph[kk][h2*2+0] = packh2(p0, p1);
                ph[kk][h2*2+1] = packh2(p2, p3);
            }
        }

        // ---- O += P V ----
        #pragma unroll
        for (int dt = 0; dt < 16; dt += 2) {
            #pragma unroll
            for (int kk = 0; kk < 4; ++kk) {
                uint32_t va = buf + VH_O + (kk*16 + (lane&15))*272
                            + dt*16 + ((lane>>4)&1)*16;
                uint32_t vv[4];
                ldsm_x4_t(vv, va);
                mma16816(o[dt],     ph[kk], vv);
                mma16816(o[dt + 1], ph[kk], vv + 2);
            }
        }
        __syncthreads();
    }

    // ---- epilogue ----
    l0 += __shfl_xor_sync(0xffffffffu, l0, 1);
    l0 += __shfl_xor_sync(0xffffffffu, l0, 2);
    l1 += __shfl_xor_sync(0xffffffffu, l1, 1);
    l1 += __shfl_xor_sync(0xffffffffu, l1, 2);
    float inv0 = 1.0f / l0, inv1 = 1.0f / l1;
    int gr0 = row0 + wm * 16 + r0;
    float* ob = out + ((size_t)bi * N_ + gr0) * DO_ + (lane & 3) * 2;
    #pragma unroll
    for (int dt = 0; dt < 16; ++dt) {
        float2 v0 = make_float2(o[dt][0] * inv0, o[dt][1] * inv0);
        float2 v1 = make_float2(o[dt][2] * inv1, o[dt][3] * inv1);
        *(float2*)(ob + dt * 8)            = v0;
        *(float2*)(ob + 8 * DO_ + dt * 8)  = v1;
    }
}

// ---------------------------------------------------------------------------
extern "C" void kernel_launch(void* const* d_in, const int* in_sizes, int n_in,
                              void* d_out, int out_size) {
    const float* h   = (const float*)d_in[0];
    const int*   adj = (const int*)  d_in[1];
    const float* Ws  = (const float*)d_in[2];
    const float* Wt  = (const float*)d_in[3];
    const float* Wc  = (const float*)d_in[4];
    float* out = (float*)d_out;

    prep_kernel<<<PACK_BLKS + B_ * N_ / 4, 256>>>(h, adj, Ws, Wt, Wc);

    cudaFuncSetAttribute(attn_kernel,
                         cudaFuncAttributeMaxDynamicSharedMemorySize, SMEM_ALLOC);
    dim3 grid(N_ / BM, B_);
    attn_kernel<<<grid, 128, SMEM_ALLOC>>>(out);
}

// round 8
// speedup vs baseline: 4.4553x; 1.0358x over previous
#include <cuda_runtime.h>
#include <cuda_fp16.h>
#include <cstdint>

#define B_   4
#define N_   4096
#define DIN_ 128
#define H_   64
#define DO_  128
#define BM   64
#define BN   64
#define NTILES 64
#define NWRD 128
#define PACK_BLKS 2048
#define PROJ_ROWS 32
#define LOG2E 1.4426950408889634f

// smem layout (bytes). Q/K rows padded to 144B, V rows to 272B
#define OFF_QH  0
#define OFF_QL  9216
#define OFF_BUF 18432
#define BUFSZ   35840
#define KH_O    0
#define KL_O    9216
#define VH_O    18432
#define SMEM_ALLOC 90112

__device__ __half g_Qh[B_*N_*H_], g_Ql[B_*N_*H_];
__device__ __half g_Kh[B_*N_*H_], g_Kl[B_*N_*H_];
__device__ __half g_Vh[B_*N_*DO_];
__device__ unsigned g_adjb[N_*NWRD];

__device__ __forceinline__ uint32_t smem_u32(const void* p) {
    uint32_t a;
    asm("{ .reg .u64 t; cvta.to.shared.u64 t, %1; cvt.u32.u64 %0, t; }" : "=r"(a) : "l"(p));
    return a;
}
__device__ __forceinline__ void mma16816(float* c, const uint32_t* a, const uint32_t* b) {
    asm volatile("mma.sync.aligned.m16n8k16.row.col.f32.f16.f16.f32 "
        "{%0,%1,%2,%3}, {%4,%5,%6,%7}, {%8,%9}, {%0,%1,%2,%3};"
        : "+f"(c[0]), "+f"(c[1]), "+f"(c[2]), "+f"(c[3])
        : "r"(a[0]), "r"(a[1]), "r"(a[2]), "r"(a[3]), "r"(b[0]), "r"(b[1]));
}
__device__ __forceinline__ void ldsm_x4(uint32_t* r, uint32_t a) {
    asm volatile("ldmatrix.sync.aligned.m8n8.x4.shared.b16 {%0,%1,%2,%3}, [%4];"
        : "=r"(r[0]), "=r"(r[1]), "=r"(r[2]), "=r"(r[3]) : "r"(a));
}
__device__ __forceinline__ void ldsm_x4_t(uint32_t* r, uint32_t a) {
    asm volatile("ldmatrix.sync.aligned.m8n8.x4.trans.shared.b16 {%0,%1,%2,%3}, [%4];"
        : "=r"(r[0]), "=r"(r[1]), "=r"(r[2]), "=r"(r[3]) : "r"(a));
}
__device__ __forceinline__ void ldsm_x2_t(uint32_t* r, uint32_t a) {
    asm volatile("ldmatrix.sync.aligned.m8n8.x2.trans.shared.b16 {%0,%1}, [%2];"
        : "=r"(r[0]), "=r"(r[1]) : "r"(a));
}
__device__ __forceinline__ void cpa16(uint32_t dst, const void* src) {
    asm volatile("cp.async.cg.shared.global [%0], [%1], 16;" :: "r"(dst), "l"(src));
}
#define CP_COMMIT() asm volatile("cp.async.commit_group;" ::: "memory")
#define CP_WAIT(n)  asm volatile("cp.async.wait_group %0;" :: "n"(n) : "memory")

__device__ __forceinline__ uint32_t cvt_h2(float hi, float lo) {
    uint32_t r;
    asm("cvt.rn.f16x2.f32 %0, %1, %2;" : "=r"(r) : "f"(hi), "f"(lo));
    return r;
}
__device__ __forceinline__ uint32_t ex2_h2(uint32_t x) {
    uint32_t r;
    asm("ex2.approx.f16x2 %0, %1;" : "=r"(r) : "r"(x));
    return r;
}
__device__ __forceinline__ uint32_t hmax2u(uint32_t a, uint32_t b) {
    __half2 r = __hmax2(*(__half2*)&a, *(__half2*)&b);
    return *(uint32_t*)&r;
}

// ============== fused prep: adj bit-pack (MLP=8) + projections ==============
__global__ __launch_bounds__(256) void prep_kernel(
    const float* __restrict__ h, const int* __restrict__ adj,
    const float* __restrict__ Ws, const float* __restrict__ Wt,
    const float* __restrict__ Wc) {
    __shared__ float sh[PROJ_ROWS][DIN_];
    const int tid = threadIdx.x;

    if (blockIdx.x < PACK_BLKS) {
        int w = blockIdx.x * 256 + tid;
        const int4* p = (const int4*)(adj + (size_t)w * 32);
        unsigned word = 0;
        #pragma unroll
        for (int j = 0; j < 8; ++j) {
            int4 v = p[j];
            unsigned nib = (unsigned)(v.x > 0) | ((unsigned)(v.y > 0) << 1) |
                           ((unsigned)(v.z > 0) << 2) | ((unsigned)(v.w > 0) << 3);
            word |= nib << (j * 4);
        }
        g_adjb[w] = word;
        return;
    }

    // ---- proj: 32 rows per block (amortize W reads over 8x more rows) ----
    const int row0 = (blockIdx.x - PACK_BLKS) * PROJ_ROWS;
    {
        const float4* src = (const float4*)(h + (size_t)row0 * DIN_);
        float4* dst = (float4*)&sh[0][0];
        for (int i = tid; i < PROJ_ROWS * DIN_ / 4; i += 256) dst[i] = src[i];
    }
    __syncthreads();

    const int c = tid;
    const float* W; int col, stride;
    if (c < 64)       { W = Ws; col = c;       stride = H_;  }
    else if (c < 128) { W = Wt; col = c - 64;  stride = H_;  }
    else              { W = Wc; col = c - 128; stride = DO_; }

    float a[PROJ_ROWS];
    #pragma unroll
    for (int r = 0; r < PROJ_ROWS; ++r) a[r] = 0.f;
    const float* wp = W + col;
    for (int k4 = 0; k4 < DIN_ / 4; ++k4) {
        float w0 = wp[(k4*4+0)*stride], w1 = wp[(k4*4+1)*stride];
        float w2 = wp[(k4*4+2)*stride], w3 = wp[(k4*4+3)*stride];
        #pragma unroll
        for (int r = 0; r < PROJ_ROWS; ++r) {
            float4 hv = *(const float4*)&sh[r][k4*4];
            a[r] = fmaf(hv.x, w0, fmaf(hv.y, w1, fmaf(hv.z, w2, fmaf(hv.w, w3, a[r]))));
        }
    }
    #pragma unroll
    for (int r = 0; r < PROJ_ROWS; ++r) {
        int rn = row0 + r;
        if (c < 64) {
            float q = a[r] * LOG2E;                   // fold log2e into Q
            __half hi = __float2half_rn(q);
            __half lo = __float2half_rn(q - __half2float(hi));
            g_Qh[(size_t)rn*H_ + col] = hi; g_Ql[(size_t)rn*H_ + col] = lo;
        } else if (c < 128) {
            __half hi = __float2half_rn(a[r]);
            __half lo = __float2half_rn(a[r] - __half2float(hi));
            g_Kh[(size_t)rn*H_ + col] = hi; g_Kl[(size_t)rn*H_ + col] = lo;
        } else {
            g_Vh[(size_t)rn*DO_ + col] = __float2half_rn(a[r]);
        }
    }
}

// ============================ attention ============================
__device__ __forceinline__ void load_tile_async(
    uint32_t bufb, int tid, const __half* Kh, const __half* Kl, const __half* Vh) {
    #pragma unroll
    for (int i = tid; i < 512; i += 128) {
        int rr = i >> 3, x = i & 7;
        cpa16(bufb + KH_O + rr*144 + x*16, Kh + rr*H_ + x*8);
        cpa16(bufb + KL_O + rr*144 + x*16, Kl + rr*H_ + x*8);
    }
    #pragma unroll
    for (int i = tid; i < 1024; i += 128) {
        int rr = i >> 4, x = i & 15;
        cpa16(bufb + VH_O + rr*272 + x*16, Vh + rr*DO_ + x*8);
    }
    // ones column (half 128 = 1.0) + zero pad (halves 129..135) for l-via-MMA
    if (tid < 64) {
        asm volatile("st.shared.v4.b32 [%0], {%1,%2,%3,%4};"
            :: "r"(bufb + VH_O + tid*272 + 256),
               "r"(0x3C00u), "r"(0u), "r"(0u), "r"(0u) : "memory");
    }
}

__global__ __launch_bounds__(128, 2) void attn_kernel(float* __restrict__ out) {
    extern __shared__ char sm[];
    const uint32_t sbase = smem_u32(sm);
    const int tid = threadIdx.x, wm = tid >> 5, lane = tid & 31;
    const int bi = blockIdx.y, row0 = blockIdx.x * BM;

    const __half* Khb = g_Kh + (size_t)bi * N_ * H_;
    const __half* Klb = g_Kl + (size_t)bi * N_ * H_;
    const __half* Vhb = g_Vh + (size_t)bi * N_ * DO_;

    {
        const __half* Qh = g_Qh + ((size_t)bi * N_ + row0) * H_;
        const __half* Ql = g_Ql + ((size_t)bi * N_ + row0) * H_;
        #pragma unroll
        for (int i = tid; i < BM * 8; i += 128) {
            int rr = i >> 3, x = i & 7;
            *(uint4*)(sm + OFF_QH + rr*144 + x*16) = *(const uint4*)(Qh + rr*H_ + x*8);
            *(uint4*)(sm + OFF_QL + rr*144 + x*16) = *(const uint4*)(Ql + rr*H_ + x*8);
        }
    }
    load_tile_async(sbase + OFF_BUF, tid, Khb, Klb, Vhb);
    CP_COMMIT();
    __syncthreads();

    uint32_t qh[4][4], ql[4][4];
    {
        int qrow = wm * 16 + (lane & 15);
        uint32_t base = sbase + qrow * 144 + ((lane >> 4) & 1) * 16;
        #pragma unroll
        for (int ks = 0; ks < 4; ++ks) {
            ldsm_x4(qh[ks], base + OFF_QH + ks * 32);
            ldsm_x4(ql[ks], base + OFF_QL + ks * 32);
        }
    }

    float o[17][4];   // o[16] = l row-sums via ones column
    #pragma unroll
    for (int d = 0; d < 17; ++d) { o[d][0]=0.f; o[d][1]=0.f; o[d][2]=0.f; o[d][3]=0.f; }
    float m0 = -1e30f, m1 = -1e30f;

    const int r0 = lane >> 2;
    const int sh2 = (lane & 3) * 2;
    const unsigned* adjr0 = g_adjb + (size_t)(row0 + wm*16 + r0) * NWRD;
    const unsigned* adjr1 = adjr0 + 8 * NWRD;

    for (int jb = 0; jb < NTILES; ++jb) {
        const uint32_t buf = sbase + OFF_BUF + (jb & 1) * BUFSZ;
        if (jb + 1 < NTILES) {
            int c1 = (jb + 1) * BN;
            load_tile_async(sbase + OFF_BUF + ((jb+1)&1)*BUFSZ, tid,
                            Khb + (size_t)c1*H_, Klb + (size_t)c1*H_, Vhb + (size_t)c1*DO_);
            CP_COMMIT();
            CP_WAIT(1);
        } else {
            CP_WAIT(0);
        }
        __syncthreads();

        // ---- S = Q K^T: 3 compensated fp16 passes (S already in log2 domain) ----
        float s[8][4];
        #pragma unroll
        for (int nt = 0; nt < 8; ++nt) { s[nt][0]=0.f; s[nt][1]=0.f; s[nt][2]=0.f; s[nt][3]=0.f; }
        #pragma unroll
        for (int ks = 0; ks < 4; ++ks) {
            #pragma unroll
            for (int nt = 0; nt < 8; ++nt) {
                uint32_t ka = buf + ((lane & 16) ? KL_O : KH_O)
                            + (nt*8 + (lane&7))*144 + ks*32 + ((lane>>3)&1)*16;
                uint32_t kb[4];
                ldsm_x4(kb, ka);
                mma16816(s[nt], qh[ks], kb);
                mma16816(s[nt], qh[ks], kb + 2);
                mma16816(s[nt], ql[ks], kb);
            }
        }

        // ---- per-thread AND-masks (half2 granularity) ----
        unsigned x00 = adjr0[jb*2] >> sh2, x01 = adjr0[jb*2+1] >> sh2;
        unsigned x10 = adjr1[jb*2] >> sh2, x11 = adjr1[jb*2+1] >> sh2;
        uint32_t am0[8], am1[8];
        #pragma unroll
        for (int nt = 0; nt < 8; ++nt) {
            unsigned b0 = ((nt < 4 ? x00 : x01) >> (8*(nt&3))) & 3u;
            unsigned b1 = ((nt < 4 ? x10 : x11) >> (8*(nt&3))) & 3u;
            am0[nt] = ((b0 & 1u) ? 0xFFFFu : 0u) | ((b0 & 2u) ? 0xFFFF0000u : 0u);
            am1[nt] = ((b1 & 1u) ? 0xFFFFu : 0u) | ((b1 & 2u) ? 0xFFFF0000u : 0u);
        }

        // ---- masked row max via HMAX2 (masked -> +0; row max >= 0 holds) ----
        uint32_t hm0 = 0u, hm1 = 0u;
        #pragma unroll
        for (int nt = 0; nt < 8; ++nt) {
            hm0 = hmax2u(hm0, cvt_h2(s[nt][1], s[nt][0]) & am0[nt]);
            hm1 = hmax2u(hm1, cvt_h2(s[nt][3], s[nt][2]) & am1[nt]);
        }
        float lm0 = fmaxf(__low2float(*(__half2*)&hm0), __high2float(*(__half2*)&hm0));
        float lm1 = fmaxf(__low2float(*(__half2*)&hm1), __high2float(*(__half2*)&hm1));
        lm0 = fmaxf(lm0, __shfl_xor_sync(0xffffffffu, lm0, 1));
        lm0 = fmaxf(lm0, __shfl_xor_sync(0xffffffffu, lm0, 2));
        lm1 = fmaxf(lm1, __shfl_xor_sync(0xffffffffu, lm1, 1));
        lm1 = fmaxf(lm1, __shfl_xor_sync(0xffffffffu, lm1, 2));
        float mn0 = fmaxf(m0, lm0), mn1 = fmaxf(m1, lm1);
        float sc0 = exp2f(m0 - mn0), sc1 = exp2f(m1 - mn1);
        m0 = mn0; m1 = mn1;
        if (sc0 != 1.f || sc1 != 1.f) {
            #pragma unroll
            for (int d = 0; d < 17; ++d) {
                o[d][0] *= sc0; o[d][1] *= sc0; o[d][2] *= sc1; o[d][3] *= sc1;
            }
        }

        // ---- P = ex2(S - m) & mask, directly as fp16x2 A-fragments ----
        uint32_t ph[4][4];
        #pragma unroll
        for (int nt = 0; nt < 8; ++nt) {
            float d0 = s[nt][0] - mn0, d1 = s[nt][1] - mn0;
            float d2 = s[nt][2] - mn1, d3 = s[nt][3] - mn1;
            ph[nt>>1][(nt&1)*2 + 0] = ex2_h2(cvt_h2(d1, d0)) & am0[nt];
            ph[nt>>1][(nt&1)*2 + 1] = ex2_h2(cvt_h2(d3, d2)) & am1[nt];
        }

        // ---- O += P V  (+ l via ones column) ----
        #pragma unroll
        for (int dt = 0; dt < 16; dt += 2) {
            #pragma unroll
            for (int kk = 0; kk < 4; ++kk) {
                uint32_t va = buf + VH_O + (kk*16 + (lane&15))*272
                            + dt*16 + ((lane>>4)&1)*16;
                uint32_t vv[4];
                ldsm_x4_t(vv, va);
                mma16816(o[dt],     ph[kk], vv);
                mma16816(o[dt + 1], ph[kk], vv + 2);
            }
        }
        #pragma unroll
        for (int kk = 0; kk < 4; ++kk) {
            uint32_t va = buf + VH_O + (kk*16 + (lane&15))*272 + 256;
            uint32_t vv[2];
            ldsm_x2_t(vv, va);
            mma16816(o[16], ph[kk], vv);
        }
        __syncthreads();
    }

    // ---- epilogue: l lives in o[16][0]/o[16][2] of quad leaders ----
    float l0 = __shfl_sync(0xffffffffu, o[16][0], lane & ~3);
    float l1 = __shfl_sync(0xffffffffu, o[16][2], lane & ~3);
    float inv0 = 1.0f / l0, inv1 = 1.0f / l1;
    int gr0 = row0 + wm * 16 + r0;
    float* ob = out + ((size_t)bi * N_ + gr0) * DO_ + sh2;
    #pragma unroll
    for (int dt = 0; dt < 16; ++dt) {
        float2 v0 = make_float2(o[dt][0] * inv0, o[dt][1] * inv0);
        float2 v1 = make_float2(o[dt][2] * inv1, o[dt][3] * inv1);
        *(float2*)(ob + dt * 8)            = v0;
        *(float2*)(ob + 8 * DO_ + dt * 8)  = v1;
    }
}

// ---------------------------------------------------------------------------
extern "C" void kernel_launch(void* const* d_in, const int* in_sizes, int n_in,
                              void* d_out, int out_size) {
    const float* h   = (const float*)d_in[0];
    const int*   adj = (const int*)  d_in[1];
    const float* Ws  = (const float*)d_in[2];
    const float* Wt  = (const float*)d_in[3];
    const float* Wc  = (const float*)d_in[4];
    float* out = (float*)d_out;

    prep_kernel<<<PACK_BLKS + B_ * N_ / PROJ_ROWS, 256>>>(h, adj, Ws, Wt, Wc);

    cudaFuncSetAttribute(attn_kernel,
                         cudaFuncAttributeMaxDynamicSharedMemorySize, SMEM_ALLOC);
    dim3 grid(N_ / BM, B_);
    attn_kernel<<<grid, 128, SMEM_ALLOC>>>(out);
}